// round 5
// baseline (speedup 1.0000x reference)
#include <cuda_runtime.h>
#include <cstdint>

// Embedding gather via bulk-copy (TMA) engine, bypassing the LSU entirely.
// out[row,:] = weight[idx[row],:], rows are 4 KB each.
// Each CTA: 1 active thread drives a ring of 8 smem slots:
//   cp.async.bulk  global->shared (mbarrier complete_tx)   [load row]
//   cp.async.bulk  shared->global (bulk_group)             [store row]
// R3/R4 showed the per-instruction LSU cost of LDG.128/STG.128 (~30k cyc/SM)
// is the limiter; the bulk engine has no per-thread issue cost.

static constexpr int EMSIZE       = 1024;
static constexpr int ROW_BYTES    = EMSIZE * 4;   // 4096
static constexpr int VOCAB        = 50257;
static constexpr int NSTAGE       = 8;            // smem ring slots (32 KB)
static constexpr int LOOKAHEAD    = 6;            // loads in flight per CTA
static constexpr int ROWS_PER_CTA = 16;

__device__ __forceinline__ uint32_t smem_u32(const void* p) {
    return (uint32_t)__cvta_generic_to_shared(p);
}

__global__ __launch_bounds__(32) void embedding_tma_kernel(
    const int* __restrict__ idx,
    const char* __restrict__ weight,
    char* __restrict__ out,
    int n_rows)
{
    __shared__ alignas(1024) char buf[NSTAGE][ROW_BYTES];
    __shared__ alignas(8) unsigned long long mbar[NSTAGE];

    if (threadIdx.x == 0) {
        #pragma unroll
        for (int s = 0; s < NSTAGE; s++) {
            uint32_t mb = smem_u32(&mbar[s]);
            asm volatile("mbarrier.init.shared.b64 [%0], 1;" :: "r"(mb) : "memory");
        }
        // Make generic-proxy mbarrier init visible to the async proxy.
        asm volatile("fence.proxy.async.shared::cta;" ::: "memory");
    }
    __syncthreads();
    if (threadIdx.x != 0) return;

    const int base = blockIdx.x * ROWS_PER_CTA;
    if (base >= n_rows) return;
    const int R = (n_rows - base < ROWS_PER_CTA) ? (n_rows - base) : ROWS_PER_CTA;

    // Preload + clamp all indices for this CTA (64 B, one-time).
    int rows[ROWS_PER_CTA];
    #pragma unroll
    for (int i = 0; i < ROWS_PER_CTA; i++) {
        int v = (i < R) ? __ldg(&idx[base + i]) : 0;
        rows[i] = (v < 0) ? 0 : (v >= VOCAB ? VOCAB - 1 : v);
    }

    // Prologue: issue LOOKAHEAD row loads.
    const int npre = (R < LOOKAHEAD) ? R : LOOKAHEAD;
    for (int j = 0; j < npre; j++) {
        int slot = j % NSTAGE;
        uint32_t mb  = smem_u32(&mbar[slot]);
        uint32_t dst = smem_u32(&buf[slot][0]);
        const char* src = weight + (size_t)rows[j] * ROW_BYTES;
        asm volatile("mbarrier.arrive.expect_tx.shared.b64 _, [%0], %1;"
                     :: "r"(mb), "r"((uint32_t)ROW_BYTES) : "memory");
        asm volatile("cp.async.bulk.shared::cluster.global.mbarrier::complete_tx::bytes "
                     "[%0], [%1], %2, [%3];"
                     :: "r"(dst), "l"(src), "r"((uint32_t)ROW_BYTES), "r"(mb) : "memory");
    }

    for (int i = 0; i < R; i++) {
        int slot = i % NSTAGE;
        uint32_t mb = smem_u32(&mbar[slot]);
        uint32_t ph = (uint32_t)((i / NSTAGE) & 1);

        // Wait for this row's load to land in smem.
        asm volatile(
            "{\n\t"
            ".reg .pred p;\n\t"
            "WAIT_%=:\n\t"
            "mbarrier.try_wait.parity.shared.b64 p, [%0], %1;\n\t"
            "@!p bra WAIT_%=;\n\t"
            "}"
            :: "r"(mb), "r"(ph) : "memory");

        // Store row to its output position (async, grouped).
        {
            uint32_t src = smem_u32(&buf[slot][0]);
            char* dst = out + (size_t)(base + i) * ROW_BYTES;
            asm volatile("cp.async.bulk.global.shared::cta.bulk_group [%0], [%1], %2;"
                         :: "l"(dst), "r"(src), "r"((uint32_t)ROW_BYTES) : "memory");
            asm volatile("cp.async.bulk.commit_group;" ::: "memory");
        }

        // Refill: load row i+LOOKAHEAD into its slot. Its previous occupant's
        // store was committed (NSTAGE-LOOKAHEAD)=2 commits ago; wait_group.read 2
        // guarantees that store has finished reading smem.
        int j = i + LOOKAHEAD;
        if (j < R) {
            asm volatile("cp.async.bulk.wait_group.read 2;" ::: "memory");
            int s2 = j % NSTAGE;
            uint32_t mb2  = smem_u32(&mbar[s2]);
            uint32_t dst2 = smem_u32(&buf[s2][0]);
            const char* src2 = weight + (size_t)rows[j] * ROW_BYTES;
            asm volatile("mbarrier.arrive.expect_tx.shared.b64 _, [%0], %1;"
                         :: "r"(mb2), "r"((uint32_t)ROW_BYTES) : "memory");
            asm volatile("cp.async.bulk.shared::cluster.global.mbarrier::complete_tx::bytes "
                         "[%0], [%1], %2, [%3];"
                         :: "r"(dst2), "l"(src2), "r"((uint32_t)ROW_BYTES), "r"(mb2) : "memory");
        }
    }

    // Drain all outstanding stores before CTA exit.
    asm volatile("cp.async.bulk.wait_group 0;" ::: "memory");
}

extern "C" void kernel_launch(void* const* d_in, const int* in_sizes, int n_in,
                              void* d_out, int out_size) {
    const int*  idx    = (const int*)d_in[0];     // (2048, 8) int32 on device
    const char* weight = (const char*)d_in[1];    // (50257, 1024) fp32
    char*       out    = (char*)d_out;            // (2048, 8, 1024) fp32

    int n_rows = in_sizes[0];                     // 16384
    int n_ctas = (n_rows + ROWS_PER_CTA - 1) / ROWS_PER_CTA;  // 1024
    embedding_tma_kernel<<<n_ctas, 32>>>(idx, weight, out, n_rows);
}

// round 6
// speedup vs baseline: 1.4757x; 1.4757x over previous
#include <cuda_runtime.h>
#include <cstdint>

// Embedding gather: out[row, :] = weight[idx[row], :]
// idx: 16384 int32, weight: 50257 x 1024 fp32, out: 16384 x 1024 fp32.
// Persistent CTAs (grid = 8 CTAs/SM x 148 SMs), grid-stride over 8-row
// batches. Each thread owns one float4 column: 8 independent LDG.128 then
// 8 streaming STG.128 per batch. R3 showed this form runs at ~91% of the
// aggregate HBM roofline; this round only removes wave-quantization.

static constexpr int EMSIZE         = 1024;
static constexpr int VEC_PER_ROW    = EMSIZE / 4;   // 256 float4 per row
static constexpr int VOCAB          = 50257;
static constexpr int ROWS_PER_BATCH = 8;
static constexpr int SMS            = 148;
static constexpr int CTAS_PER_SM    = 8;

__global__ __launch_bounds__(256) void embedding_gather_kernel(
    const int* __restrict__ idx,
    const float4* __restrict__ weight,
    float4* __restrict__ out,
    int n_rows)
{
    const int t      = threadIdx.x;                     // column (0..255)
    const int stride = gridDim.x * ROWS_PER_BATCH;

    for (int base = blockIdx.x * ROWS_PER_BATCH; base < n_rows; base += stride) {
        if (base + ROWS_PER_BATCH <= n_rows) {
            int r[ROWS_PER_BATCH];
            #pragma unroll
            for (int i = 0; i < ROWS_PER_BATCH; i++) {
                int v = __ldg(&idx[base + i]);
                r[i] = (v < 0) ? 0 : (v >= VOCAB ? VOCAB - 1 : v);
            }
            float4 w[ROWS_PER_BATCH];
            #pragma unroll
            for (int i = 0; i < ROWS_PER_BATCH; i++)
                w[i] = __ldg(&weight[(size_t)r[i] * VEC_PER_ROW + t]);
            #pragma unroll
            for (int i = 0; i < ROWS_PER_BATCH; i++)
                __stcs(&out[(size_t)(base + i) * VEC_PER_ROW + t], w[i]);
        } else {
            for (int i = 0; i < ROWS_PER_BATCH; i++) {
                int row = base + i;
                if (row >= n_rows) break;
                int v = __ldg(&idx[row]);
                v = (v < 0) ? 0 : (v >= VOCAB ? VOCAB - 1 : v);
                float4 w = __ldg(&weight[(size_t)v * VEC_PER_ROW + t]);
                __stcs(&out[(size_t)row * VEC_PER_ROW + t], w);
            }
        }
    }
}

extern "C" void kernel_launch(void* const* d_in, const int* in_sizes, int n_in,
                              void* d_out, int out_size) {
    const int*    idx    = (const int*)d_in[0];     // (2048, 8) int32 on device
    const float4* weight = (const float4*)d_in[1];  // (50257, 1024) fp32
    float4*       out    = (float4*)d_out;          // (2048, 8, 1024) fp32

    int n_rows    = in_sizes[0];                    // 16384
    int n_batches = (n_rows + ROWS_PER_BATCH - 1) / ROWS_PER_BATCH;  // 2048
    int n_ctas    = SMS * CTAS_PER_SM;              // 1184 persistent CTAs
    if (n_ctas > n_batches) n_ctas = n_batches;
    embedding_gather_kernel<<<n_ctas, 256>>>(idx, weight, out, n_rows);
}

// round 7
// speedup vs baseline: 1.5009x; 1.0171x over previous
#include <cuda_runtime.h>
#include <cstdint>

// Embedding gather: out[row, :] = weight[idx[row], :]
// idx: 16384 int32, weight: 50257 x 1024 fp32, out: 16384 x 1024 fp32.
// One CTA per 8 rows (2048 CTAs); each thread owns one float4 column:
// 8 independent LDG.128 then 8 streaming STG.128.
// Steady-state this runs at ~97% of aggregate HBM (reads in-kernel, store
// drain overlapping the next replay via L2) — measured best of all variants
// (R3: 16.86us vs TMA 25.3, persistent 17.15, low-occ 18.5).

static constexpr int EMSIZE       = 1024;
static constexpr int VEC_PER_ROW  = EMSIZE / 4;   // 256 float4 per row
static constexpr int VOCAB        = 50257;
static constexpr int ROWS_PER_CTA = 8;

__global__ __launch_bounds__(256) void embedding_gather_kernel(
    const int* __restrict__ idx,
    const float4* __restrict__ weight,
    float4* __restrict__ out,
    int n_rows)
{
    const int t    = threadIdx.x;                       // column (0..255)
    const int base = blockIdx.x * ROWS_PER_CTA;

    if (base + ROWS_PER_CTA <= n_rows) {
        // 8 indices as two vector loads (broadcast within CTA).
        const int4* ip = (const int4*)(idx + base);
        int4 i0 = __ldg(&ip[0]);
        int4 i1 = __ldg(&ip[1]);
        int r[ROWS_PER_CTA] = { i0.x, i0.y, i0.z, i0.w, i1.x, i1.y, i1.z, i1.w };
        #pragma unroll
        for (int i = 0; i < ROWS_PER_CTA; i++) {
            int v = r[i];
            r[i] = (v < 0) ? 0 : (v >= VOCAB ? VOCAB - 1 : v);
        }
        float4 w[ROWS_PER_CTA];
        #pragma unroll
        for (int i = 0; i < ROWS_PER_CTA; i++)
            w[i] = __ldg(&weight[(size_t)r[i] * VEC_PER_ROW + t]);
        #pragma unroll
        for (int i = 0; i < ROWS_PER_CTA; i++)
            __stcs(&out[(size_t)(base + i) * VEC_PER_ROW + t], w[i]);
    } else {
        // Tail (unused for 16384 rows, kept for safety).
        for (int i = 0; i < ROWS_PER_CTA; i++) {
            int row = base + i;
            if (row >= n_rows) break;
            int v = __ldg(&idx[row]);
            v = (v < 0) ? 0 : (v >= VOCAB ? VOCAB - 1 : v);
            float4 w = __ldg(&weight[(size_t)v * VEC_PER_ROW + t]);
            __stcs(&out[(size_t)row * VEC_PER_ROW + t], w);
        }
    }
}

extern "C" void kernel_launch(void* const* d_in, const int* in_sizes, int n_in,
                              void* d_out, int out_size) {
    const int*    idx    = (const int*)d_in[0];     // (2048, 8) int32 on device
    const float4* weight = (const float4*)d_in[1];  // (50257, 1024) fp32
    float4*       out    = (float4*)d_out;          // (2048, 8, 1024) fp32

    int n_rows = in_sizes[0];                       // 16384
    int n_ctas = (n_rows + ROWS_PER_CTA - 1) / ROWS_PER_CTA;  // 2048
    embedding_gather_kernel<<<n_ctas, 256>>>(idx, weight, out, n_rows);
}